// round 10
// baseline (speedup 1.0000x reference)
#include <cuda_runtime.h>
#include <math.h>
#include <stdint.h>

#define EPSN 1e-12f

__device__ __forceinline__ float tf32_rnd(float a) {
    uint32_t u;
    asm("cvt.rna.tf32.f32 %0, %1;" : "=r"(u) : "f"(a));
    return __uint_as_float(u);
}

__device__ __forceinline__ void mma_tf32(float* c, const uint32_t* a, const uint32_t* b) {
    asm("mma.sync.aligned.m16n8k8.row.col.f32.tf32.tf32.f32 "
        "{%0,%1,%2,%3}, {%4,%5,%6,%7}, {%8,%9}, {%0,%1,%2,%3};"
        : "+f"(c[0]), "+f"(c[1]), "+f"(c[2]), "+f"(c[3])
        : "r"(a[0]), "r"(a[1]), "r"(a[2]), "r"(a[3]), "r"(b[0]), "r"(b[1]));
}

// Banded cost volume via warp-level tf32 MMA (3xTF32 split ~ fp32 precision).
//
// One CTA = one (n, h, x-tile of TX=128). Channels in passes of CB=32.
// Tiles staged K-major as float2 (tf32 hi, lo) with pair-stride CP=36 and an
// XOR swizzle on the channel index, chosen so staging stores, MMA fragment
// loads, AND norm reads are all shared-memory bank-conflict-free.
//
//   dot[x, col] = sum_c L[x,c] * R[col,c],  col = x_local + (D-1) - d
//
// Each warp owns a 16-row x-tile and sweeps NJT j-tiles of 8 covering its
// band slice [xw0, xw0 + D + 14]. Accumulators live in registers (f32).
// Epilogue: normalize by per-column inverse L2 norms (accumulated in regs
// from the staged tiles each pass), mask x<d, bounce through an smem sOut
// buffer (aliases the dead tiles) and store coalesced float4, streaming.

template<int C, int D, int TX, int N, int NT>
__global__ __launch_bounds__(NT, 2)
void cv_mma_kernel(const float* __restrict__ Lp, const float* __restrict__ Rp,
                   float* __restrict__ out, int H, int W)
{
    constexpr int CB  = 32;                 // channels per pass
    constexpr int CP  = 36;                 // float2 pair stride per row
    constexpr int NJT = (D + 22) / 8;       // j-tiles: ceil((D+15)/8)
    constexpr int SOP = TX + 4;             // sOut row stride (floats)
    constexpr int NPASS = C / CB;
    static_assert(TX == 128 && NT == 256, "fixed tiling");
    static_assert(N >= TX + D - 1, "halo");
    static_assert(16 * (NT / 32) == TX, "one m-tile per warp");
    static_assert(8 * NJT >= D + 15, "band coverage");
    static_assert(112 + 8 * NJT - 1 <= N - 1, "halo stage bound");

    constexpr int OF_SR   = TX * CP * 8;            // bytes
    constexpr int OF_INVL = OF_SR + N * CP * 8;
    constexpr int OF_INVR = OF_INVL + TX * 4;
    static_assert(D * SOP * 4 <= OF_INVL, "sOut aliases tiles only");

    extern __shared__ __align__(16) char smem[];
    float2* sl   = (float2*)smem;                   // [TX][CP] (hi,lo)
    float2* sr   = (float2*)(smem + OF_SR);         // [N][CP]
    float*  invl = (float*)(smem + OF_INVL);        // TX
    float*  invr = (float*)(smem + OF_INVR);        // N
    float*  sOut = (float*)smem;                    // D*SOP, aliases tiles

    const int tid  = threadIdx.x;
    const int wid  = tid >> 5;
    const int lane = tid & 31;
    const int gid  = lane >> 2;      // 0..7
    const int tig  = lane & 3;       // 0..3

    const int n  = blockIdx.z;
    const int h  = blockIdx.y;
    const int xb = blockIdx.x * TX;
    const int HW = H * W;
    const int plane = ((n * C) * H + h) * W;
    const int y0 = xb - (D - 1);

    const int xw0     = wid * 16;    // warp's x-tile base (8 warps x 16 = 128)
    const int colbase = xw0;         // band start for this warp

    // swizzled pair index: row * CP + (c ^ ((row>>2)&7))
    #define SWZI(row, c) ((row) * CP + ((c) ^ (((row) >> 2) & 7)))

    float acc[NJT][4];
    #pragma unroll
    for (int t = 0; t < NJT; ++t)
        #pragma unroll
        for (int q = 0; q < 4; ++q) acc[t][q] = 0.0f;

    float ssA = 0.0f, ssB = 0.0f;    // per-column sum-of-squares partials

    #pragma unroll 1
    for (int pass = 0; pass < NPASS; ++pass) {
        if (pass) __syncthreads();   // previous pass done reading tiles
        const int cg = pass * CB;

        // ---- stage L tile: hi/lo split, swizzled float2 stores ----
        #pragma unroll 1
        for (int idx = tid; idx < CB * TX; idx += NT) {
            int c = idx >> 7, x = idx & 127;
            float a = Lp[plane + (cg + c) * HW + xb + x];
            float hi = tf32_rnd(a), lo = tf32_rnd(a - hi);
            sl[SWZI(x, c)] = make_float2(hi, lo);
        }
        // ---- stage R halo ----
        #pragma unroll 1
        for (int idx = tid; idx < CB * N; idx += NT) {
            int c = idx / N, col = idx % N;
            int y = y0 + col;
            float a = (y >= 0 && y < W) ? Rp[plane + (cg + c) * HW + y] : 0.0f;
            float hi = tf32_rnd(a), lo = tf32_rnd(a - hi);
            sr[SWZI(col, c)] = make_float2(hi, lo);
        }
        __syncthreads();

        // ---- accumulate per-column sum of squares ----
        if (tid < TX) {
            float s = ssA;
            #pragma unroll
            for (int c = 0; c < CB; ++c) {
                float2 p = sl[SWZI(tid, c)];
                float v = p.x + p.y;
                s = fmaf(v, v, s);
            }
            ssA = s;
        }
        if (tid < N) {
            float s = ssB;
            #pragma unroll
            for (int c = 0; c < CB; ++c) {
                float2 p = sr[SWZI(tid, c)];
                float v = p.x + p.y;
                s = fmaf(v, v, s);
            }
            ssB = s;
        }

        // ---- banded MMA sweep: 3xTF32 split ----
        #pragma unroll
        for (int kc = 0; kc < CB / 8; ++kc) {
            const int k0 = kc * 8;
            float2 pa0 = sl[SWZI(xw0 + gid,     k0 + tig)];
            float2 pa1 = sl[SWZI(xw0 + gid + 8, k0 + tig)];
            float2 pa2 = sl[SWZI(xw0 + gid,     k0 + tig + 4)];
            float2 pa3 = sl[SWZI(xw0 + gid + 8, k0 + tig + 4)];
            uint32_t ah[4] = {__float_as_uint(pa0.x), __float_as_uint(pa1.x),
                              __float_as_uint(pa2.x), __float_as_uint(pa3.x)};
            uint32_t al[4] = {__float_as_uint(pa0.y), __float_as_uint(pa1.y),
                              __float_as_uint(pa2.y), __float_as_uint(pa3.y)};
            #pragma unroll
            for (int t = 0; t < NJT; ++t) {
                const int col = colbase + 8 * t + gid;
                float2 pb0 = sr[SWZI(col, k0 + tig)];
                float2 pb1 = sr[SWZI(col, k0 + tig + 4)];
                uint32_t bh[2] = {__float_as_uint(pb0.x), __float_as_uint(pb1.x)};
                uint32_t bl[2] = {__float_as_uint(pb0.y), __float_as_uint(pb1.y)};
                mma_tf32(acc[t], ah, bh);
                mma_tf32(acc[t], ah, bl);
                mma_tf32(acc[t], al, bh);
            }
        }
    }

    // ---- finalize inverse norms (non-aliased region) ----
    if (tid < TX) invl[tid] = 1.0f / fmaxf(sqrtf(ssA), EPSN);
    if (tid < N)  invr[tid] = 1.0f / fmaxf(sqrtf(ssB), EPSN);
    __syncthreads();   // all tile reads done; inv arrays visible

    // ---- epilogue: normalize + mask + diagonal STS into sOut ----
    const int xl0 = xw0 + gid, xl8 = xl0 + 8;
    const float il0 = invl[xl0], il8 = invl[xl8];

    #pragma unroll
    for (int t = 0; t < NJT; ++t) {
        const int col0 = colbase + 8 * t + 2 * tig;
        const int col1 = col0 + 1;
        const float ir0 = invr[col0], ir1 = invr[col1];
        int d;
        d = xl0 + (D - 1) - col0;
        if (d >= 0 && d < D)
            sOut[d * SOP + xl0] = (xb + xl0 >= d) ? acc[t][0] * il0 * ir0 : 0.0f;
        d = xl0 + (D - 1) - col1;
        if (d >= 0 && d < D)
            sOut[d * SOP + xl0] = (xb + xl0 >= d) ? acc[t][1] * il0 * ir1 : 0.0f;
        d = xl8 + (D - 1) - col0;
        if (d >= 0 && d < D)
            sOut[d * SOP + xl8] = (xb + xl8 >= d) ? acc[t][2] * il8 * ir0 : 0.0f;
        d = xl8 + (D - 1) - col1;
        if (d >= 0 && d < D)
            sOut[d * SOP + xl8] = (xb + xl8 >= d) ? acc[t][3] * il8 * ir1 : 0.0f;
    }
    __syncthreads();

    // ---- coalesced streaming writeout ----
    #pragma unroll 1
    for (int idx = tid; idx < D * (TX / 4); idx += NT) {
        int d = idx >> 5, q = idx & 31;
        float4 v = *(float4*)&sOut[d * SOP + 4 * q];
        __stcs((float4*)&out[(((size_t)n * D + d) * H + h) * W + xb + 4 * q], v);
    }
    #undef SWZI
}

template<int C, int D, int TX, int N, int NT>
static void launch_level(const float* l, const float* r, float* o,
                         int H, int W, int nb)
{
    constexpr int CP = 36;
    constexpr int SMB = TX * CP * 8 + N * CP * 8 + TX * 4 + N * 4;
    auto k = cv_mma_kernel<C, D, TX, N, NT>;
    cudaFuncSetAttribute(k, cudaFuncAttributeMaxDynamicSharedMemorySize, SMB);
    k<<<dim3(W / TX, H, nb), NT, SMB>>>(l, r, o, H, W);
}

extern "C" void kernel_launch(void* const* d_in, const int* in_sizes, int n_in,
                              void* d_out, int out_size)
{
    const float* l0 = (const float*)d_in[0];
    const float* r0 = (const float*)d_in[1];
    const float* l1 = (const float*)d_in[2];
    const float* r1 = (const float*)d_in[3];
    const float* l2 = (const float*)d_in[4];
    const float* r2 = (const float*)d_in[5];
    float* out = (float*)d_out;

    // max_disparity = 128 (fixed by setup_inputs); per-level D = 128, 64, 32.
    float* out1 = out + (size_t)2 * 128 * 256 * 512;
    float* out2 = out1 + (size_t)2 * 64 * 128 * 256;

    launch_level<32, 128, 128, 256, 256>(l0, r0, out,  256, 512, 2);
    launch_level<64,  64, 128, 192, 256>(l1, r1, out1, 128, 256, 2);
    launch_level<96,  32, 128, 160, 256>(l2, r2, out2,  64, 128, 2);
}

// round 12
// speedup vs baseline: 1.4432x; 1.4432x over previous
#include <cuda_runtime.h>
#include <math.h>
#include <stdint.h>

#define EPSN 1e-12f

__device__ __forceinline__ float tf32_rnd(float a) {
    uint32_t u;
    asm("cvt.rna.tf32.f32 %0, %1;" : "=r"(u) : "f"(a));
    return __uint_as_float(u);
}

__device__ __forceinline__ void mma_tf32(float* c, const uint32_t* a, const uint32_t* b) {
    asm("mma.sync.aligned.m16n8k8.row.col.f32.tf32.tf32.f32 "
        "{%0,%1,%2,%3}, {%4,%5,%6,%7}, {%8,%9}, {%0,%1,%2,%3};"
        : "+f"(c[0]), "+f"(c[1]), "+f"(c[2]), "+f"(c[3])
        : "r"(a[0]), "r"(a[1]), "r"(a[2]), "r"(a[3]), "r"(b[0]), "r"(b[1]));
}

// Banded cost volume via warp-level tf32 MMA (3xTF32 split ~ fp32 precision).
//
// One CTA = one (n, h, x-tile of TX=128). Channels in passes of CB=32.
// Tiles staged K-major as float2 (tf32 hi, lo), pair stride CP=36, XOR
// swizzle on the channel index (bank-conflict-free staging + fragment loads).
//
//   dot[x, col] = sum_c L[x,c] * R[col,c],  col = x_local + (D-1) - d
//
// NT=512: 16 warps. Warp w = (x-tile (w>>1)*16, j-half w&1). Each warp
// sweeps NJTH = NJT/2 j-tiles of 8 -> 36 accumulator floats max (vs 72 in
// the unsplit version), which is the difference between 512 and 1024
// resident threads per SM.

template<int C, int D, int TX, int N, int NT>
__global__ __launch_bounds__(NT, 2)
void cv_mma_kernel(const float* __restrict__ Lp, const float* __restrict__ Rp,
                   float* __restrict__ out, int H, int W)
{
    constexpr int CB   = 32;                 // channels per pass
    constexpr int CP   = 36;                 // float2 pair stride per row
    constexpr int NJT  = (D + 22) / 8;       // total j-tiles: ceil((D+15)/8)
    constexpr int NJTH = NJT / 2;            // per-warp j-tiles
    constexpr int SOP  = TX + 4;             // sOut row stride (floats)
    constexpr int NPASS = C / CB;
    static_assert(TX == 128 && NT == 512, "fixed tiling");
    static_assert(N >= TX + D - 1, "halo");
    static_assert((NJT % 2) == 0, "even j-split");
    static_assert(16 * (NT / 64) == TX, "x-tiles cover TX");
    static_assert(8 * NJT >= D + 15, "band coverage");
    static_assert(112 + 8 * NJT - 1 <= N - 1, "halo stage bound");

    constexpr int OF_SR   = TX * CP * 8;             // bytes
    constexpr int OF_INVL = OF_SR + N * CP * 8;
    constexpr int OF_INVR = OF_INVL + TX * 4;
    static_assert(D * SOP * 4 <= OF_INVL, "sOut aliases tiles only");

    extern __shared__ __align__(16) char smem[];
    float2* sl   = (float2*)smem;                    // [TX][CP] (hi,lo)
    float2* sr   = (float2*)(smem + OF_SR);          // [N][CP]
    float*  invl = (float*)(smem + OF_INVL);         // TX
    float*  invr = (float*)(smem + OF_INVR);         // N
    float*  sOut = (float*)smem;                     // D*SOP, aliases tiles

    const int tid  = threadIdx.x;
    const int wid  = tid >> 5;
    const int lane = tid & 31;
    const int gid  = lane >> 2;      // 0..7
    const int tig  = lane & 3;       // 0..3

    const int n  = blockIdx.z;
    const int h  = blockIdx.y;
    const int xb = blockIdx.x * TX;
    const int HW = H * W;
    const int plane = ((n * C) * H + h) * W;
    const int y0 = xb - (D - 1);

    const int xw0     = (wid >> 1) * 16;             // warp's x-tile base
    const int colbase = xw0 + (wid & 1) * (8 * NJTH); // warp's j-half base

    // swizzled pair index: row * CP + (c ^ ((row>>2)&7))
    #define SWZI(row, c) ((row) * CP + ((c) ^ (((row) >> 2) & 7)))

    float acc[NJTH][4];
    #pragma unroll
    for (int t = 0; t < NJTH; ++t)
        #pragma unroll
        for (int q = 0; q < 4; ++q) acc[t][q] = 0.0f;

    float ssA = 0.0f, ssB = 0.0f;    // per-column sum-of-squares partials

    #pragma unroll 1
    for (int pass = 0; pass < NPASS; ++pass) {
        if (pass) __syncthreads();   // previous pass done reading tiles
        const int cg = pass * CB;

        // ---- stage L tile: hi/lo split, swizzled float2 stores ----
        #pragma unroll 1
        for (int idx = tid; idx < CB * TX; idx += NT) {
            int c = idx >> 7, x = idx & 127;
            float a = Lp[plane + (cg + c) * HW + xb + x];
            float hi = tf32_rnd(a), lo = tf32_rnd(a - hi);
            sl[SWZI(x, c)] = make_float2(hi, lo);
        }
        // ---- stage R halo ----
        #pragma unroll 1
        for (int idx = tid; idx < CB * N; idx += NT) {
            int c = idx / N, col = idx % N;
            int y = y0 + col;
            float a = (y >= 0 && y < W) ? Rp[plane + (cg + c) * HW + y] : 0.0f;
            float hi = tf32_rnd(a), lo = tf32_rnd(a - hi);
            sr[SWZI(col, c)] = make_float2(hi, lo);
        }
        __syncthreads();

        // ---- accumulate per-column sum of squares ----
        if (tid < TX) {
            float s = ssA;
            #pragma unroll
            for (int c = 0; c < CB; ++c) {
                float2 p = sl[SWZI(tid, c)];
                float v = p.x + p.y;
                s = fmaf(v, v, s);
            }
            ssA = s;
        }
        if (tid < N) {
            float s = ssB;
            #pragma unroll
            for (int c = 0; c < CB; ++c) {
                float2 p = sr[SWZI(tid, c)];
                float v = p.x + p.y;
                s = fmaf(v, v, s);
            }
            ssB = s;
        }

        // ---- banded MMA sweep: 3xTF32 split ----
        #pragma unroll
        for (int kc = 0; kc < CB / 8; ++kc) {
            const int k0 = kc * 8;
            float2 pa0 = sl[SWZI(xw0 + gid,     k0 + tig)];
            float2 pa1 = sl[SWZI(xw0 + gid + 8, k0 + tig)];
            float2 pa2 = sl[SWZI(xw0 + gid,     k0 + tig + 4)];
            float2 pa3 = sl[SWZI(xw0 + gid + 8, k0 + tig + 4)];
            uint32_t ah[4] = {__float_as_uint(pa0.x), __float_as_uint(pa1.x),
                              __float_as_uint(pa2.x), __float_as_uint(pa3.x)};
            uint32_t al[4] = {__float_as_uint(pa0.y), __float_as_uint(pa1.y),
                              __float_as_uint(pa2.y), __float_as_uint(pa3.y)};
            #pragma unroll
            for (int t = 0; t < NJTH; ++t) {
                const int col = colbase + 8 * t + gid;
                float2 pb0 = sr[SWZI(col, k0 + tig)];
                float2 pb1 = sr[SWZI(col, k0 + tig + 4)];
                uint32_t bh[2] = {__float_as_uint(pb0.x), __float_as_uint(pb1.x)};
                uint32_t bl[2] = {__float_as_uint(pb0.y), __float_as_uint(pb1.y)};
                mma_tf32(acc[t], ah, bh);
                mma_tf32(acc[t], ah, bl);
                mma_tf32(acc[t], al, bh);
            }
        }
    }

    // ---- finalize inverse norms (non-aliased region) ----
    if (tid < TX) invl[tid] = 1.0f / fmaxf(sqrtf(ssA), EPSN);
    if (tid < N)  invr[tid] = 1.0f / fmaxf(sqrtf(ssB), EPSN);
    __syncthreads();   // all tile reads done; inv arrays visible

    // ---- epilogue: normalize + mask + diagonal STS into sOut ----
    const int xl0 = xw0 + gid, xl8 = xl0 + 8;
    const float il0 = invl[xl0], il8 = invl[xl8];

    #pragma unroll
    for (int t = 0; t < NJTH; ++t) {
        const int col0 = colbase + 8 * t + 2 * tig;
        const int col1 = col0 + 1;
        const float ir0 = invr[col0], ir1 = invr[col1];
        int d;
        d = xl0 + (D - 1) - col0;
        if (d >= 0 && d < D)
            sOut[d * SOP + xl0] = (xb + xl0 >= d) ? acc[t][0] * il0 * ir0 : 0.0f;
        d = xl0 + (D - 1) - col1;
        if (d >= 0 && d < D)
            sOut[d * SOP + xl0] = (xb + xl0 >= d) ? acc[t][1] * il0 * ir1 : 0.0f;
        d = xl8 + (D - 1) - col0;
        if (d >= 0 && d < D)
            sOut[d * SOP + xl8] = (xb + xl8 >= d) ? acc[t][2] * il8 * ir0 : 0.0f;
        d = xl8 + (D - 1) - col1;
        if (d >= 0 && d < D)
            sOut[d * SOP + xl8] = (xb + xl8 >= d) ? acc[t][3] * il8 * ir1 : 0.0f;
    }
    __syncthreads();

    // ---- coalesced streaming writeout ----
    #pragma unroll 1
    for (int idx = tid; idx < D * (TX / 4); idx += NT) {
        int d = idx >> 5, q = idx & 31;
        float4 v = *(float4*)&sOut[d * SOP + 4 * q];
        __stcs((float4*)&out[(((size_t)n * D + d) * H + h) * W + xb + 4 * q], v);
    }
    #undef SWZI
}

template<int C, int D, int TX, int N, int NT>
static void launch_level(const float* l, const float* r, float* o,
                         int H, int W, int nb)
{
    constexpr int CP = 36;
    constexpr int SMB = TX * CP * 8 + N * CP * 8 + TX * 4 + N * 4;
    auto k = cv_mma_kernel<C, D, TX, N, NT>;
    cudaFuncSetAttribute(k, cudaFuncAttributeMaxDynamicSharedMemorySize, SMB);
    k<<<dim3(W / TX, H, nb), NT, SMB>>>(l, r, o, H, W);
}

extern "C" void kernel_launch(void* const* d_in, const int* in_sizes, int n_in,
                              void* d_out, int out_size)
{
    const float* l0 = (const float*)d_in[0];
    const float* r0 = (const float*)d_in[1];
    const float* l1 = (const float*)d_in[2];
    const float* r1 = (const float*)d_in[3];
    const float* l2 = (const float*)d_in[4];
    const float* r2 = (const float*)d_in[5];
    float* out = (float*)d_out;

    // max_disparity = 128 (fixed by setup_inputs); per-level D = 128, 64, 32.
    float* out1 = out + (size_t)2 * 128 * 256 * 512;
    float* out2 = out1 + (size_t)2 * 64 * 128 * 256;

    launch_level<32, 128, 128, 256, 512>(l0, r0, out,  256, 512, 2);
    launch_level<64,  64, 128, 192, 512>(l1, r1, out1, 128, 256, 2);
    launch_level<96,  32, 128, 160, 512>(l2, r2, out2,  64, 128, 2);
}

// round 15
// speedup vs baseline: 1.6949x; 1.1744x over previous
#include <cuda_runtime.h>
#include <math.h>
#include <stdint.h>

#define EPSN 1e-12f

__device__ __forceinline__ float tf32_rnd(float a) {
    uint32_t u;
    asm("cvt.rna.tf32.f32 %0, %1;" : "=r"(u) : "f"(a));
    return __uint_as_float(u);
}

__device__ __forceinline__ void mma_tf32(float* c, const uint32_t* a, const uint32_t* b) {
    asm("mma.sync.aligned.m16n8k8.row.col.f32.tf32.tf32.f32 "
        "{%0,%1,%2,%3}, {%4,%5,%6,%7}, {%8,%9}, {%0,%1,%2,%3};"
        : "+f"(c[0]), "+f"(c[1]), "+f"(c[2]), "+f"(c[3])
        : "r"(a[0]), "r"(a[1]), "r"(a[2]), "r"(a[3]), "r"(b[0]), "r"(b[1]));
}

// Banded cost volume via warp-level tf32 MMA (3xTF32 split ~ fp32 precision).
// One CTA = one (n, h, x-tile of 128). Channels in passes of CB=32.
// Tiles staged K-major as float2 (tf32 hi, lo), pair stride CP=36, XOR
// swizzle on the channel index (conflict-free staging + fragment loads).
// Fragment addresses use the identity (k0 + t) ^ sw == k0 + (t ^ sw)
// (k0 mult of 8, t^sw < 8): all MMA-loop addresses are precomputed bases
// plus compile-time immediates -> no per-iteration ALU.
// 16 warps: warp w = (x-tile (w>>1)*16, j-half w&1), NJTH j-tiles each.

template<int C, int D, int N>
__device__ __forceinline__ void cv_level(const float* __restrict__ Lp,
                                         const float* __restrict__ Rp,
                                         float* __restrict__ out,
                                         int H, int W, int bx, int h, int n,
                                         char* smem)
{
    constexpr int TX = 128, NT = 512, CB = 32, CP = 36;
    constexpr int NJT  = (D + 22) / 8;       // total j-tiles: ceil((D+15)/8)
    constexpr int NJTH = NJT / 2;            // per-warp j-tiles
    constexpr int SOP  = TX + 4;             // sOut row stride (floats)
    constexpr int NPASS = C / CB;
    static_assert(N >= TX + D - 1, "halo");
    static_assert((NJT % 2) == 0, "even j-split");
    static_assert(8 * NJT >= D + 15, "band coverage");
    static_assert(112 + 8 * NJT - 1 <= N - 1, "halo stage bound");

    constexpr int OF_SR   = TX * CP * 8;             // bytes
    constexpr int OF_INVL = OF_SR + N * CP * 8;
    constexpr int OF_INVR = OF_INVL + TX * 4;
    static_assert(D * SOP * 4 <= OF_INVL, "sOut aliases tiles only");

    float2* sl   = (float2*)smem;                    // [TX][CP] (hi,lo)
    float2* sr   = (float2*)(smem + OF_SR);          // [N][CP]
    float*  invl = (float*)(smem + OF_INVL);         // TX
    float*  invr = (float*)(smem + OF_INVR);         // N
    float*  sOut = (float*)smem;                     // D*SOP, aliases tiles

    const int tid  = threadIdx.x;
    const int wid  = tid >> 5;
    const int lane = tid & 31;
    const int gid  = lane >> 2;      // 0..7
    const int tig  = lane & 3;       // 0..3

    const int xb = bx * TX;
    const int HW = H * W;
    const int plane = ((n * C) * H + h) * W;
    const int y0 = xb - (D - 1);

    const int xw0     = (wid >> 1) * 16;
    const int colbase = xw0 + (wid & 1) * (8 * NJTH);   // multiple of 8

    // staging swizzle: row * CP + (c ^ ((row>>2)&7))
    #define SWZI(row, c) ((row) * CP + ((c) ^ (((row) >> 2) & 7)))

    // ---- pass-invariant fragment pair-index bases ----
    const int rA0 = xw0 + gid, rA1 = rA0 + 8;
    const int swA0 = (rA0 >> 2) & 7, swA1 = (rA1 >> 2) & 7;
    const int iA00 = rA0 * CP + (tig ^ swA0);
    const int iA04 = rA0 * CP + ((tig + 4) ^ swA0);
    const int iA10 = rA1 * CP + (tig ^ swA1);
    const int iA14 = rA1 * CP + ((tig + 4) ^ swA1);

    const int rB0 = colbase + gid;                   // j-tile 0 row
    const int sB0 = (rB0 >> 2) & 7;                  // exact: colbase mult 8
    int iB0[4], iB4[4];                              // swizzle cycles period 4
    #pragma unroll
    for (int j = 0; j < 4; ++j) {
        int sw = (sB0 + 2 * j) & 7;
        iB0[j] = rB0 * CP + (tig ^ sw);
        iB4[j] = rB0 * CP + ((tig + 4) ^ sw);
    }

    float acc[NJTH][4];
    #pragma unroll
    for (int t = 0; t < NJTH; ++t)
        #pragma unroll
        for (int q = 0; q < 4; ++q) acc[t][q] = 0.0f;

    float ssA = 0.0f, ssB = 0.0f;

    #pragma unroll 1
    for (int pass = 0; pass < NPASS; ++pass) {
        if (pass) __syncthreads();
        const int cg = pass * CB;

        // ---- stage L tile ----
        #pragma unroll 1
        for (int idx = tid; idx < CB * TX; idx += NT) {
            int c = idx >> 7, x = idx & 127;
            float a = Lp[plane + (cg + c) * HW + xb + x];
            float hi = tf32_rnd(a), lo = tf32_rnd(a - hi);
            sl[SWZI(x, c)] = make_float2(hi, lo);
        }
        // ---- stage R halo ----
        #pragma unroll 1
        for (int idx = tid; idx < CB * N; idx += NT) {
            int c = idx / N, col = idx % N;
            int y = y0 + col;
            float a = (y >= 0 && y < W) ? Rp[plane + (cg + c) * HW + y] : 0.0f;
            float hi = tf32_rnd(a), lo = tf32_rnd(a - hi);
            sr[SWZI(col, c)] = make_float2(hi, lo);
        }
        __syncthreads();

        // ---- per-column sum of squares ----
        if (tid < TX) {
            float s = ssA;
            #pragma unroll
            for (int c = 0; c < CB; ++c) {
                float2 p = sl[SWZI(tid, c)];
                float v = p.x + p.y;
                s = fmaf(v, v, s);
            }
            ssA = s;
        }
        if (tid < N) {
            float s = ssB;
            #pragma unroll
            for (int c = 0; c < CB; ++c) {
                float2 p = sr[SWZI(tid, c)];
                float v = p.x + p.y;
                s = fmaf(v, v, s);
            }
            ssB = s;
        }

        // ---- banded MMA sweep: 3xTF32 split, zero per-iter address ALU ----
        #pragma unroll
        for (int kc = 0; kc < CB / 8; ++kc) {
            const int k0 = kc * 8;
            float2 pa0 = sl[iA00 + k0];
            float2 pa1 = sl[iA10 + k0];
            float2 pa2 = sl[iA04 + k0];
            float2 pa3 = sl[iA14 + k0];
            uint32_t ah[4] = {__float_as_uint(pa0.x), __float_as_uint(pa1.x),
                              __float_as_uint(pa2.x), __float_as_uint(pa3.x)};
            uint32_t al[4] = {__float_as_uint(pa0.y), __float_as_uint(pa1.y),
                              __float_as_uint(pa2.y), __float_as_uint(pa3.y)};
            #pragma unroll
            for (int t = 0; t < NJTH; ++t) {
                const int tb = t * 8 * CP + k0;      // compile-time constant
                float2 pb0 = sr[iB0[t & 3] + tb];
                float2 pb1 = sr[iB4[t & 3] + tb];
                uint32_t bh[2] = {__float_as_uint(pb0.x), __float_as_uint(pb1.x)};
                uint32_t bl[2] = {__float_as_uint(pb0.y), __float_as_uint(pb1.y)};
                mma_tf32(acc[t], ah, bh);
                mma_tf32(acc[t], ah, bl);
                mma_tf32(acc[t], al, bh);
            }
        }
    }

    // ---- finalize inverse norms ----
    if (tid < TX) invl[tid] = 1.0f / fmaxf(sqrtf(ssA), EPSN);
    if (tid < N)  invr[tid] = 1.0f / fmaxf(sqrtf(ssB), EPSN);
    __syncthreads();

    // ---- epilogue: normalize + mask + diagonal STS into sOut ----
    const int xl0 = xw0 + gid, xl8 = xl0 + 8;
    const float il0 = invl[xl0], il8 = invl[xl8];

    #pragma unroll
    for (int t = 0; t < NJTH; ++t) {
        const int col0 = colbase + 8 * t + 2 * tig;
        const int col1 = col0 + 1;
        const float ir0 = invr[col0], ir1 = invr[col1];
        int d;
        d = xl0 + (D - 1) - col0;
        if (d >= 0 && d < D)
            sOut[d * SOP + xl0] = (xb + xl0 >= d) ? acc[t][0] * il0 * ir0 : 0.0f;
        d = xl0 + (D - 1) - col1;
        if (d >= 0 && d < D)
            sOut[d * SOP + xl0] = (xb + xl0 >= d) ? acc[t][1] * il0 * ir1 : 0.0f;
        d = xl8 + (D - 1) - col0;
        if (d >= 0 && d < D)
            sOut[d * SOP + xl8] = (xb + xl8 >= d) ? acc[t][2] * il8 * ir0 : 0.0f;
        d = xl8 + (D - 1) - col1;
        if (d >= 0 && d < D)
            sOut[d * SOP + xl8] = (xb + xl8 >= d) ? acc[t][3] * il8 * ir1 : 0.0f;
    }
    __syncthreads();

    // ---- coalesced streaming writeout ----
    #pragma unroll 1
    for (int idx = tid; idx < D * (TX / 4); idx += NT) {
        int d = idx >> 5, q = idx & 31;
        float4 v = *(float4*)&sOut[d * SOP + 4 * q];
        __stcs((float4*)&out[(((size_t)n * D + d) * H + h) * W + xb + 4 * q], v);
    }
    #undef SWZI
}

// Fused launch: all three pyramid levels in one grid so they overlap.
// Long blocks (L1: 2 passes, L2: 3 passes) are scheduled first; L0 fills in.
//   [0, 512):    level 1  (bx in {0,1}, H=128, n in {0,1})
//   [512, 640):  level 2  (bx=0, H=64)
//   [640, 2688): level 0  (bx in 0..3, H=256)
__global__ __launch_bounds__(512, 2)
void cv_fused_kernel(const float* __restrict__ l0, const float* __restrict__ r0,
                     const float* __restrict__ l1, const float* __restrict__ r1,
                     const float* __restrict__ l2, const float* __restrict__ r2,
                     float* __restrict__ o0, float* __restrict__ o1,
                     float* __restrict__ o2)
{
    extern __shared__ __align__(16) char smem[];
    const int b = blockIdx.x;
    if (b >= 640) {
        const int bb = b - 640;
        cv_level<32, 128, 256>(l0, r0, o0, 256, 512, bb & 3, (bb >> 2) & 255, bb >> 10, smem);
    } else if (b < 512) {
        cv_level<64, 64, 192>(l1, r1, o1, 128, 256, b & 1, (b >> 1) & 127, b >> 8, smem);
    } else {
        const int bb = b - 512;
        cv_level<96, 32, 160>(l2, r2, o2, 64, 128, 0, bb & 63, bb >> 6, smem);
    }
}

extern "C" void kernel_launch(void* const* d_in, const int* in_sizes, int n_in,
                              void* d_out, int out_size)
{
    const float* l0 = (const float*)d_in[0];
    const float* r0 = (const float*)d_in[1];
    const float* l1 = (const float*)d_in[2];
    const float* r1 = (const float*)d_in[3];
    const float* l2 = (const float*)d_in[4];
    const float* r2 = (const float*)d_in[5];
    float* out = (float*)d_out;

    // max_disparity = 128 (fixed by setup_inputs); per-level D = 128, 64, 32.
    float* out1 = out + (size_t)2 * 128 * 256 * 512;
    float* out2 = out1 + (size_t)2 * 64 * 128 * 256;

    // smem = level-0 requirement (the max): 128*36*8 + 256*36*8 + 128*4 + 256*4
    constexpr int SMB = 128 * 36 * 8 + 256 * 36 * 8 + 128 * 4 + 256 * 4; // 112128
    cudaFuncSetAttribute(cv_fused_kernel,
                         cudaFuncAttributeMaxDynamicSharedMemorySize, SMB);
    cv_fused_kernel<<<2688, 512, SMB>>>(l0, r0, l1, r1, l2, r2, out, out1, out2);
}

// round 16
// speedup vs baseline: 3.8503x; 2.2717x over previous
#include <cuda_runtime.h>
#include <math.h>
#include <stdint.h>

#define EPSN 1e-12f

// pack two f32 -> bf16x2 (lo = g0, hi = g1)
__device__ __forceinline__ uint32_t pack_bf16x2(float g1, float g0) {
    uint32_t r;
    asm("cvt.rn.bf16x2.f32 %0, %1, %2;" : "=r"(r) : "f"(g1), "f"(g0));
    return r;
}

__device__ __forceinline__ void mma_bf16(float* c, const uint32_t* a, const uint32_t* b) {
    asm("mma.sync.aligned.m16n8k16.row.col.f32.bf16.bf16.f32 "
        "{%0,%1,%2,%3}, {%4,%5,%6,%7}, {%8,%9}, {%0,%1,%2,%3};"
        : "+f"(c[0]), "+f"(c[1]), "+f"(c[2]), "+f"(c[3])
        : "r"(a[0]), "r"(a[1]), "r"(a[2]), "r"(a[3]), "r"(b[0]), "r"(b[1]));
}

// Banded cost volume via m16n8k16 bf16 MMA, 3xBF16 split (Ah*Bh + Ah*Bl + Al*Bh).
// One CTA = one (n, h, x-tile of 128). Channels in passes of CB=32 = 16 bf16x2
// channel-pairs; hi and lo matrices staged as separate word tiles with row
// stride CPP=17 (odd => staging stores conflict-free; frag loads <= 2-way).
// Per-column L2 norms accumulated in registers DURING staging (exact fp32),
// reduced through a small smem partial array at the end.
// 16 warps: warp w = (x-tile (w>>1)*16, j-half w&1), NJTH j-tiles each.
// Epilogue: normalize + mask, bounce through smem sOut (aliasing dead tiles)
// in NDR d-rounds, then coalesced streaming float4 stores.

template<int C, int D, int N, int NDR>
__device__ __forceinline__ void cv_level(const float* __restrict__ Lp,
                                         const float* __restrict__ Rp,
                                         float* __restrict__ out,
                                         int H, int W, int bx, int h, int n,
                                         char* smem)
{
    constexpr int TX = 128, NT = 512, CB = 32, CPP = 17;
    constexpr int NJT  = (D + 22) / 8;
    constexpr int NJTH = NJT / 2;
    constexpr int SOP  = TX + 4;
    constexpr int NPASS = C / CB;
    constexpr int DH = D / NDR;
    static_assert((NJT % 2) == 0, "even j-split");
    static_assert(8 * NJT >= D + 15, "band coverage");
    static_assert(112 + 8 * NJTH + 8 * NJTH - 1 <= N - 1, "halo bound");

    // word-addressed tile map
    constexpr int WA    = TX * CPP;              // words per A tile
    constexpr int WB    = N * CPP;
    constexpr int OF_AH = 0;
    constexpr int OF_AL = WA;
    constexpr int OF_BH = 2 * WA;
    constexpr int OF_BL = 2 * WA + WB;
    constexpr int TILE_END = 2 * WA + 2 * WB;    // words
    constexpr int OF_INVL = TILE_END;
    constexpr int OF_INVR = TILE_END + TX;
    static_assert(DH * SOP <= TILE_END, "sOut alias fits");

    uint32_t* sw = (uint32_t*)smem;
    float*    sf = (float*)smem;

    const int tid  = threadIdx.x;
    const int wid  = tid >> 5;
    const int lane = tid & 31;
    const int gid  = lane >> 2;
    const int tig  = lane & 3;

    const int xb = bx * TX;
    const int HW = H * W;
    const int plane = ((n * C) * H + h) * W;
    const int y0 = xb - (D - 1);

    const int xw0     = (wid >> 1) * 16;
    const int colbase = xw0 + (wid & 1) * (8 * NJTH);

    const int iA = (xw0 + gid) * CPP + tig;      // +8*CPP row half, +4 k half
    const int iB = (colbase + gid) * CPP + tig;

    float acc[NJTH][4];
    #pragma unroll
    for (int t = 0; t < NJTH; ++t)
        #pragma unroll
        for (int q = 0; q < 4; ++q) acc[t][q] = 0.0f;

    float ssA = 0.0f, ssB = 0.0f;

    // staging thread maps (pass-invariant => register ss accumulation)
    const int axc = tid & 127, agrp = tid >> 7;          // A: column, cp-group
    const int bactive = (tid < 2 * N);
    const int bcol = bactive ? (tid % N) : 0;
    const int bgrp = bactive ? (tid / N) : 0;
    const int by   = y0 + bcol;
    const int bok  = bactive && (by >= 0) && (by < W);

    #pragma unroll 1
    for (int pass = 0; pass < NPASS; ++pass) {
        if (pass) __syncthreads();
        const int cg = pass * CB;

        // ---- stage A (L tile): 4 channel-pairs per thread ----
        {
            const float* lp = Lp + plane + xb + axc + (size_t)cg * HW;
            #pragma unroll
            for (int j = 0; j < 4; ++j) {
                const int cp = agrp * 4 + j;
                float g0 = lp[(2 * cp) * HW];
                float g1 = lp[(2 * cp + 1) * HW];
                uint32_t hi = pack_bf16x2(g1, g0);
                float h0 = __uint_as_float(hi << 16);
                float h1 = __uint_as_float(hi & 0xFFFF0000u);
                uint32_t lo = pack_bf16x2(g1 - h1, g0 - h0);
                const int a = axc * CPP + cp;
                sw[OF_AH + a] = hi;
                sw[OF_AL + a] = lo;
                ssA = fmaf(g0, g0, ssA);
                ssA = fmaf(g1, g1, ssA);
            }
        }
        // ---- stage B (R halo): 8 channel-pairs per active thread ----
        if (bactive) {
            const float* rp = Rp + plane + by + (size_t)cg * HW;
            #pragma unroll
            for (int j = 0; j < 8; ++j) {
                const int cp = bgrp * 8 + j;
                float g0 = bok ? rp[(2 * cp) * HW] : 0.0f;
                float g1 = bok ? rp[(2 * cp + 1) * HW] : 0.0f;
                uint32_t hi = pack_bf16x2(g1, g0);
                float h0 = __uint_as_float(hi << 16);
                float h1 = __uint_as_float(hi & 0xFFFF0000u);
                uint32_t lo = pack_bf16x2(g1 - h1, g0 - h0);
                const int a = bcol * CPP + cp;
                sw[OF_BH + a] = hi;
                sw[OF_BL + a] = lo;
                ssB = fmaf(g0, g0, ssB);
                ssB = fmaf(g1, g1, ssB);
            }
        }
        __syncthreads();

        // ---- banded MMA sweep: 3xBF16 split, k16 ----
        #pragma unroll
        for (int kc = 0; kc < 2; ++kc) {
            const int ko = kc * 8;
            uint32_t ah[4], al[4];
            ah[0] = sw[OF_AH + iA + ko];
            ah[1] = sw[OF_AH + iA + 8 * CPP + ko];
            ah[2] = sw[OF_AH + iA + ko + 4];
            ah[3] = sw[OF_AH + iA + 8 * CPP + ko + 4];
            al[0] = sw[OF_AL + iA + ko];
            al[1] = sw[OF_AL + iA + 8 * CPP + ko];
            al[2] = sw[OF_AL + iA + ko + 4];
            al[3] = sw[OF_AL + iA + 8 * CPP + ko + 4];
            #pragma unroll
            for (int t = 0; t < NJTH; ++t) {
                const int tb = iB + t * 8 * CPP + ko;
                uint32_t bh[2] = {sw[OF_BH + tb], sw[OF_BH + tb + 4]};
                uint32_t bl[2] = {sw[OF_BL + tb], sw[OF_BL + tb + 4]};
                mma_bf16(acc[t], ah, bh);
                mma_bf16(acc[t], ah, bl);
                mma_bf16(acc[t], al, bh);
            }
        }
    }

    // ---- reduce per-column norms through smem partials (alias dead tiles) ----
    __syncthreads();                     // MMA done reading tiles
    sf[tid] = ssA;                       // partA: words [0, 512)
    if (bactive) sf[512 + tid] = ssB;    // partB: words [512, 1024)
    __syncthreads();
    if (tid < TX) {
        float s = sf[tid] + sf[tid + 128] + sf[tid + 256] + sf[tid + 384];
        sf[OF_INVL + tid] = 1.0f / fmaxf(sqrtf(s), EPSN);
    }
    if (tid < N) {
        float s = sf[512 + tid] + sf[512 + tid + N];
        sf[OF_INVR + tid] = 1.0f / fmaxf(sqrtf(s), EPSN);
    }
    __syncthreads();

    // ---- epilogue: NDR d-rounds of normalize + mask + sOut bounce ----
    const int xl0 = xw0 + gid, xl8 = xl0 + 8;
    const float il0 = sf[OF_INVL + xl0], il8 = sf[OF_INVL + xl8];

    #pragma unroll
    for (int r = 0; r < NDR; ++r) {
        const int dlo = r * DH;
        #pragma unroll
        for (int t = 0; t < NJTH; ++t) {
            const int col0 = colbase + 8 * t + 2 * tig;
            const int col1 = col0 + 1;
            const float ir0 = sf[OF_INVR + col0], ir1 = sf[OF_INVR + col1];
            int d;
            d = xl0 + (D - 1) - col0;
            if (d >= dlo && d < dlo + DH)
                sf[(d - dlo) * SOP + xl0] = (xb + xl0 >= d) ? acc[t][0] * il0 * ir0 : 0.0f;
            d = xl0 + (D - 1) - col1;
            if (d >= dlo && d < dlo + DH)
                sf[(d - dlo) * SOP + xl0] = (xb + xl0 >= d) ? acc[t][1] * il0 * ir1 : 0.0f;
            d = xl8 + (D - 1) - col0;
            if (d >= dlo && d < dlo + DH)
                sf[(d - dlo) * SOP + xl8] = (xb + xl8 >= d) ? acc[t][2] * il8 * ir0 : 0.0f;
            d = xl8 + (D - 1) - col1;
            if (d >= dlo && d < dlo + DH)
                sf[(d - dlo) * SOP + xl8] = (xb + xl8 >= d) ? acc[t][3] * il8 * ir1 : 0.0f;
        }
        __syncthreads();

        #pragma unroll 1
        for (int idx = tid; idx < DH * (TX / 4); idx += NT) {
            int d = idx >> 5, q = idx & 31;
            float4 v = *(float4*)&sf[d * SOP + 4 * q];
            __stcs((float4*)&out[(((size_t)n * D + dlo + d) * H + h) * W + xb + 4 * q], v);
        }
        __syncthreads();
    }
}

// Fused launch: all three pyramid levels in one grid.
// Long blocks (L1: 2 passes, L2: 3 passes) first; L0 fills in.
//   [0, 512):    level 1  (bx in {0,1}, H=128, n in {0,1})
//   [512, 640):  level 2  (bx=0, H=64)
//   [640, 2688): level 0  (bx in 0..3, H=256)
__global__ __launch_bounds__(512, 2)
void cv_fused_kernel(const float* __restrict__ l0, const float* __restrict__ r0,
                     const float* __restrict__ l1, const float* __restrict__ r1,
                     const float* __restrict__ l2, const float* __restrict__ r2,
                     float* __restrict__ o0, float* __restrict__ o1,
                     float* __restrict__ o2)
{
    extern __shared__ __align__(16) char smem[];
    const int b = blockIdx.x;
    if (b >= 640) {
        const int bb = b - 640;
        cv_level<32, 128, 256, 2>(l0, r0, o0, 256, 512, bb & 3, (bb >> 2) & 255, bb >> 10, smem);
    } else if (b < 512) {
        cv_level<64, 64, 192, 1>(l1, r1, o1, 128, 256, b & 1, (b >> 1) & 127, b >> 8, smem);
    } else {
        const int bb = b - 512;
        cv_level<96, 32, 160, 1>(l2, r2, o2, 64, 128, 0, bb & 63, bb >> 6, smem);
    }
}

extern "C" void kernel_launch(void* const* d_in, const int* in_sizes, int n_in,
                              void* d_out, int out_size)
{
    const float* l0 = (const float*)d_in[0];
    const float* r0 = (const float*)d_in[1];
    const float* l1 = (const float*)d_in[2];
    const float* r1 = (const float*)d_in[3];
    const float* l2 = (const float*)d_in[4];
    const float* r2 = (const float*)d_in[5];
    float* out = (float*)d_out;

    // max_disparity = 128 (fixed by setup_inputs); per-level D = 128, 64, 32.
    float* out1 = out + (size_t)2 * 128 * 256 * 512;
    float* out2 = out1 + (size_t)2 * 64 * 128 * 256;

    // smem = level-0 requirement (max): (2*128*17 + 2*256*17 + 128 + 256) words
    constexpr int SMB = (2 * 128 * 17 + 2 * 256 * 17 + 128 + 256) * 4;  // 53760 B
    cudaFuncSetAttribute(cv_fused_kernel,
                         cudaFuncAttributeMaxDynamicSharedMemorySize, SMB);
    cv_fused_kernel<<<2688, 512, SMB>>>(l0, r0, l1, r1, l2, r2, out, out1, out2);
}